// round 15
// baseline (speedup 1.0000x reference)
#include <cuda_runtime.h>
#include <cuda_bf16.h>
#include <math.h>
#include <stdint.h>

#define ROWS 16384
#define H 1024
#define KTOT 3072
#define T 37
#define LP 39
#define SEQ 512
#define NB 32
#define WPAD 1032

// ---------------- scratch (static device memory; no allocations) ----------------
__device__ __align__(16) __nv_bfloat16 g_Ahi[(size_t)ROWS * KTOT];  // 96 MB
__device__ __align__(16) __nv_bfloat16 g_Alo[(size_t)ROWS * KTOT];  // 96 MB
__device__ __align__(16) __nv_bfloat16 g_Bhi[(size_t)H * KTOT];     // 6 MB  (W_cat^T hi)
__device__ __align__(16) __nv_bfloat16 g_Blo[(size_t)H * KTOT];     // 6 MB  (W_cat^T lo)
__device__ float g_y[(size_t)ROWS * H];                             // 64 MB

// ---------------- helpers ----------------
__device__ __forceinline__ uint32_t smem_u32(const void* p) {
    uint32_t a;
    asm("{ .reg .u64 t; cvta.to.shared.u64 t, %1; cvt.u32.u64 %0, t; }" : "=r"(a) : "l"(p));
    return a;
}
#define SMEM_SW(b) ((b) ^ (((b) >> 3) & 0x70))

__device__ __forceinline__ void cp16(uint32_t dst, const void* src) {
    asm volatile("cp.async.cg.shared.global [%0], [%1], 16;" :: "r"(dst), "l"(src) : "memory");
}

#define LDSM_X4(r0, r1, r2, r3, addr) \
    asm volatile("ldmatrix.sync.aligned.m8n8.x4.shared.b16 {%0,%1,%2,%3}, [%4];" \
        : "=r"(r0), "=r"(r1), "=r"(r2), "=r"(r3) : "r"(addr))

#define MMA16816(d, a, b) \
    asm volatile("mma.sync.aligned.m16n8k16.row.col.f32.bf16.bf16.f32 " \
        "{%0,%1,%2,%3}, {%4,%5,%6,%7}, {%8,%9}, {%0,%1,%2,%3};" \
        : "+f"(d[0]), "+f"(d[1]), "+f"(d[2]), "+f"(d[3]) \
        : "r"(a[0]), "r"(a[1]), "r"(a[2]), "r"(a[3]), "r"(b[0]), "r"(b[1]))

// split fp32x4 -> bf16 hi/lo packed
__device__ __forceinline__ void cvt_hilo(float4 v, uint2 &uhi, uint2 &ulo) {
    __nv_bfloat162 h01 = __floats2bfloat162_rn(v.x, v.y);
    __nv_bfloat162 h23 = __floats2bfloat162_rn(v.z, v.w);
    float2 f01 = __bfloat1622float2(h01), f23 = __bfloat1622float2(h23);
    __nv_bfloat162 l01 = __floats2bfloat162_rn(v.x - f01.x, v.y - f01.y);
    __nv_bfloat162 l23 = __floats2bfloat162_rn(v.z - f23.x, v.w - f23.y);
    uhi.x = *(uint32_t*)&h01; uhi.y = *(uint32_t*)&h23;
    ulo.x = *(uint32_t*)&l01; ulo.y = *(uint32_t*)&l23;
}

// =================================================================================
// KW: W_cat [3072,1024] fp32  ->  g_Bhi/g_Blo [1024,3072] bf16 (transposed split)
// =================================================================================
__global__ void kw_split(const float* __restrict__ W)
{
    __shared__ float tile[32][33];
    int k0 = blockIdx.x * 32, n0 = blockIdx.y * 32;
    int tx = threadIdx.x, ty = threadIdx.y;
    for (int r = ty; r < 32; r += 8) tile[r][tx] = W[(size_t)(k0 + r) * H + n0 + tx];
    __syncthreads();
    for (int r = ty; r < 32; r += 8) {
        float v = tile[tx][r];
        __nv_bfloat16 hi = __float2bfloat16(v);
        float lo = v - __bfloat162float(hi);
        size_t o = (size_t)(n0 + r) * KTOT + k0 + tx;
        g_Bhi[o] = hi;
        g_Blo[o] = __float2bfloat16(lo);
    }
}

// =================================================================================
// K1: attn over bio (37 classes); emits bf16 hi/lo of [h | aware | h*aware]
// =================================================================================
__global__ __launch_bounds__(256) void k1_attn(const float* __restrict__ h,
                                               const float* __restrict__ bio)
{
    extern __shared__ float bio_sm[];               // [37][1024]
    __shared__ float2 attn_sm[8][T];
    int tid = threadIdx.x;

    const float4* bio4 = (const float4*)bio;
    float4* bs4 = (float4*)bio_sm;
    for (int i = tid; i < T * H / 4; i += 256) bs4[i] = bio4[i];
    __syncthreads();

    int warp = tid >> 5, lane = tid & 31;
    int r0 = (blockIdx.x * 8 + warp) * 2;
    const float4* h0 = (const float4*)(h + (size_t)r0 * H);
    const float4* h1 = h0 + H / 4;
    float4 x0[8], x1[8];
#pragma unroll
    for (int i = 0; i < 8; i++) { x0[i] = h0[lane + 32*i]; x1[i] = h1[lane + 32*i]; }

    for (int t = 0; t < T; t++) {
        const float4* br = (const float4*)(bio_sm + t * H);
        float p0 = 0.f, p1 = 0.f;
#pragma unroll
        for (int i = 0; i < 8; i++) {
            float4 b = br[lane + 32*i];
            p0 += x0[i].x*b.x + x0[i].y*b.y + x0[i].z*b.z + x0[i].w*b.w;
            p1 += x1[i].x*b.x + x1[i].y*b.y + x1[i].z*b.z + x1[i].w*b.w;
        }
#pragma unroll
        for (int o = 16; o; o >>= 1) {
            p0 += __shfl_xor_sync(0xffffffffu, p0, o);
            p1 += __shfl_xor_sync(0xffffffffu, p1, o);
        }
        if (lane == 0) attn_sm[warp][t] = make_float2(p0 * 0.03125f, p1 * 0.03125f);
    }
    __syncwarp();

    float m0 = -1e30f, m1 = -1e30f;
    for (int t = 0; t < T; t++) { float2 v = attn_sm[warp][t]; m0 = fmaxf(m0, v.x); m1 = fmaxf(m1, v.y); }
    float sum0 = 0.f, sum1 = 0.f;
    for (int t = 0; t < T; t++) { float2 v = attn_sm[warp][t]; sum0 += expf(v.x - m0); sum1 += expf(v.y - m1); }
    float inv0 = 1.f / sum0, inv1 = 1.f / sum1;
    __syncwarp();
    for (int t = lane; t < T; t += 32) {
        float2 v = attn_sm[warp][t];
        attn_sm[warp][t] = make_float2(expf(v.x - m0) * inv0, expf(v.y - m1) * inv1);
    }
    __syncwarp();

    size_t ro0 = (size_t)r0 * KTOT, ro1 = (size_t)(r0 + 1) * KTOT;
#pragma unroll 2
    for (int i = 0; i < 8; i++) {
        float4 a0 = make_float4(0,0,0,0), a1 = make_float4(0,0,0,0);
        for (int t = 0; t < T; t++) {
            float2 at = attn_sm[warp][t];
            float4 b = ((const float4*)(bio_sm + t * H))[lane + 32*i];
            a0.x += at.x*b.x; a0.y += at.x*b.y; a0.z += at.x*b.z; a0.w += at.x*b.w;
            a1.x += at.y*b.x; a1.y += at.y*b.y; a1.z += at.y*b.z; a1.w += at.y*b.w;
        }
        float4 q0, q1;
        q0.x = x0[i].x*a0.x; q0.y = x0[i].y*a0.y; q0.z = x0[i].z*a0.z; q0.w = x0[i].w*a0.w;
        q1.x = x1[i].x*a1.x; q1.y = x1[i].y*a1.y; q1.z = x1[i].z*a1.z; q1.w = x1[i].w*a1.w;

        int col = (lane + 32*i) * 4;
        uint2 uh, ul;
        cvt_hilo(x0[i], uh, ul);
        *(uint2*)(g_Ahi + ro0 + col) = uh; *(uint2*)(g_Alo + ro0 + col) = ul;
        cvt_hilo(x1[i], uh, ul);
        *(uint2*)(g_Ahi + ro1 + col) = uh; *(uint2*)(g_Alo + ro1 + col) = ul;
        cvt_hilo(a0, uh, ul);
        *(uint2*)(g_Ahi + ro0 + 1024 + col) = uh; *(uint2*)(g_Alo + ro0 + 1024 + col) = ul;
        cvt_hilo(a1, uh, ul);
        *(uint2*)(g_Ahi + ro1 + 1024 + col) = uh; *(uint2*)(g_Alo + ro1 + 1024 + col) = ul;
        cvt_hilo(q0, uh, ul);
        *(uint2*)(g_Ahi + ro0 + 2048 + col) = uh; *(uint2*)(g_Alo + ro0 + 2048 + col) = ul;
        cvt_hilo(q1, uh, ul);
        *(uint2*)(g_Ahi + ro1 + 2048 + col) = uh; *(uint2*)(g_Alo + ro1 + 2048 + col) = ul;
    }
}

// =================================================================================
// K2: y = gelu( x @ W_cat + b ) via mma.sync bf16 split-3 (K'' = 9216)
// BM=128, BN=256, BK=64, 3-stage cp.async ring. Warp grid 2(M)x4(N): warp tile
// 64x64 -> 4x8 mma fragments, 128 f32 accums. Halves A-side LTS traffic vs BN=128.
// =================================================================================
#define BM 128
#define BN 256
#define BK 64
#define NS 3
#define KTILES 144         /* 9216 / 64 */
#define SM_A    0
#define SM_ASZ  (BM * BK * 2)                 /* 16384 */
#define SM_B    (NS * SM_ASZ)                 /* 49152 */
#define SM_BSZ  (BN * BK * 2)                 /* 32768 */
#define SM_TOT  (SM_B + NS * SM_BSZ)          /* 147456 */

__device__ __forceinline__ void load_tile(uint32_t sb, int slot, int kt,
                                          int m0, int n0, int tid)
{
    int seg = kt / 48;
    int kk = (kt - seg * 48) * 64;
    const __nv_bfloat16* As = (seg < 2) ? g_Ahi : g_Alo;
    const __nv_bfloat16* Bs = (seg == 1) ? g_Blo : g_Bhi;
    uint32_t abase = sb + SM_A + slot * SM_ASZ;
    uint32_t bbase = sb + SM_B + slot * SM_BSZ;
#pragma unroll
    for (int j = 0; j < 4; j++) {
        int idx = tid + j * 256;
        int row = idx >> 3, ch = idx & 7;
        cp16(abase + SMEM_SW(row * 128 + ch * 16),
             As + (size_t)(m0 + row) * KTOT + kk + ch * 8);
    }
#pragma unroll
    for (int j = 0; j < 8; j++) {
        int idx = tid + j * 256;
        int row = idx >> 3, ch = idx & 7;
        cp16(bbase + SMEM_SW(row * 128 + ch * 16),
             Bs + (size_t)(n0 + row) * KTOT + kk + ch * 8);
    }
}

__global__ __launch_bounds__(256, 1) void k2_mma(const float* __restrict__ bias)
{
    extern __shared__ char smem[];
    uint32_t sb = smem_u32(smem);
    int tid = threadIdx.x, warp = tid >> 5, lane = tid & 31;
    int m0 = blockIdx.y * BM, n0 = blockIdx.x * BN;
    int wm = warp & 1, wn = warp >> 1;        // warp tile (wm*64, wn*64)

    float acc[4][8][4];
#pragma unroll
    for (int mi = 0; mi < 4; mi++)
#pragma unroll
        for (int ni = 0; ni < 8; ni++)
#pragma unroll
            for (int j = 0; j < 4; j++) acc[mi][ni][j] = 0.f;

    int a_row = (lane & 7) + ((lane >> 3) & 1) * 8;   // 0..15
    int a_kch = lane >> 4;                            // 0..1
    int b_row = (lane & 7) + (lane >> 4) * 8;         // n 0..15
    int b_kch = (lane >> 3) & 1;                      // 0..1

#pragma unroll
    for (int p = 0; p < NS; p++) {
        load_tile(sb, p, p, m0, n0, tid);
        asm volatile("cp.async.commit_group;" ::: "memory");
    }

    for (int kt = 0; kt < KTILES; kt++) {
        int slot = kt - (kt / NS) * NS;
        if (kt < KTILES - 2)       asm volatile("cp.async.wait_group 2;" ::: "memory");
        else if (kt == KTILES - 2) asm volatile("cp.async.wait_group 1;" ::: "memory");
        else                       asm volatile("cp.async.wait_group 0;" ::: "memory");
        __syncthreads();

        uint32_t abase = sb + SM_A + slot * SM_ASZ;
        uint32_t bbase = sb + SM_B + slot * SM_BSZ;
#pragma unroll
        for (int ks = 0; ks < 4; ks++) {
            uint32_t A[4][4];
#pragma unroll
            for (int mi = 0; mi < 4; mi++) {
                int row = wm * 64 + mi * 16 + a_row;
                uint32_t addr = abase + SMEM_SW((uint32_t)(row * 128 + ks * 32 + a_kch * 16));
                LDSM_X4(A[mi][0], A[mi][1], A[mi][2], A[mi][3], addr);
            }
            uint32_t B[8][2];
#pragma unroll
            for (int np = 0; np < 4; np++) {
                int row = wn * 64 + np * 16 + b_row;
                uint32_t addr = bbase + SMEM_SW((uint32_t)(row * 128 + ks * 32 + b_kch * 16));
                uint32_t r0, r1, r2, r3;
                LDSM_X4(r0, r1, r2, r3, addr);
                B[np*2][0] = r0;   B[np*2][1] = r1;
                B[np*2+1][0] = r2; B[np*2+1][1] = r3;
            }
#pragma unroll
            for (int mi = 0; mi < 4; mi++)
#pragma unroll
                for (int ni = 0; ni < 8; ni++)
                    MMA16816(acc[mi][ni], A[mi], B[ni]);
        }
        __syncthreads();

        if (kt + NS < KTILES) {
            load_tile(sb, slot, kt + NS, m0, n0, tid);
            asm volatile("cp.async.commit_group;" ::: "memory");
        }
    }

    int g = lane >> 2, tig = lane & 3;
#pragma unroll
    for (int mi = 0; mi < 4; mi++) {
        int row0 = m0 + wm * 64 + mi * 16 + g;
#pragma unroll
        for (int ni = 0; ni < 8; ni++) {
            int col = n0 + wn * 64 + ni * 8 + tig * 2;
            float2 bv = *(const float2*)&bias[col];
            float x, y0v, y1v;
            x = acc[mi][ni][0] + bv.x; y0v = 0.5f * x * (1.f + erff(x * 0.70710678118654752440f));
            x = acc[mi][ni][1] + bv.y; y1v = 0.5f * x * (1.f + erff(x * 0.70710678118654752440f));
            *(float2*)(g_y + (size_t)row0 * H + col) = make_float2(y0v, y1v);
            x = acc[mi][ni][2] + bv.x; y0v = 0.5f * x * (1.f + erff(x * 0.70710678118654752440f));
            x = acc[mi][ni][3] + bv.y; y1v = 0.5f * x * (1.f + erff(x * 0.70710678118654752440f));
            *(float2*)(g_y + (size_t)(row0 + 8) * H + col) = make_float2(y0v, y1v);
        }
    }
}

// =================================================================================
// K3: logits = y @ W_crf + b_crf ; ner_scores = [logits | -1e4 pads] (B*S x 39)
// =================================================================================
__global__ __launch_bounds__(256) void k3_logits(const float* __restrict__ Wc,
                                                 const float* __restrict__ bc,
                                                 float* __restrict__ out)
{
    extern __shared__ float wsm[];   // [37][WPAD]
    int tid = threadIdx.x;
    for (int i = tid; i < H * T; i += 256) {
        int k = i / T, t = i - k * T;
        wsm[t * WPAD + k] = Wc[i];
    }
    __syncthreads();

    int warp = tid >> 5, lane = tid & 31;
    int slot = blockIdx.x * 8 + warp;
    for (int rep = 0; rep < 8; rep++) {
        int r0 = slot * 16 + rep * 2;
        const float4* y0 = (const float4*)(g_y + (size_t)r0 * H);
        const float4* y1 = y0 + H / 4;
        float4 x0[8], x1[8];
#pragma unroll
        for (int i = 0; i < 8; i++) { x0[i] = y0[lane + 32*i]; x1[i] = y1[lane + 32*i]; }
        for (int t = 0; t < T; t++) {
            const float4* wr = (const float4*)(wsm + t * WPAD);
            float p0 = 0.f, p1 = 0.f;
#pragma unroll
            for (int i = 0; i < 8; i++) {
                float4 w = wr[lane + 32*i];
                p0 += x0[i].x*w.x + x0[i].y*w.y + x0[i].z*w.z + x0[i].w*w.w;
                p1 += x1[i].x*w.x + x1[i].y*w.y + x1[i].z*w.z + x1[i].w*w.w;
            }
#pragma unroll
            for (int o = 16; o; o >>= 1) {
                p0 += __shfl_xor_sync(0xffffffffu, p0, o);
                p1 += __shfl_xor_sync(0xffffffffu, p1, o);
            }
            if (lane == 0) {
                float bt = __ldg(&bc[t]);
                out[(size_t)r0 * LP + t]       = p0 + bt;
                out[(size_t)(r0 + 1) * LP + t] = p1 + bt;
            }
        }
        if (lane < 2) {
            out[(size_t)r0 * LP + T + lane]       = -10000.f;
            out[(size_t)(r0 + 1) * LP + T + lane] = -10000.f;
        }
    }
}

// =================================================================================
// K4: CRF log-likelihood; one warp per batch (R11 version)
// =================================================================================
__global__ __launch_bounds__(32) void k4_crf(const float* __restrict__ scores,
                                             const int* __restrict__ labels,
                                             const int* __restrict__ lens,
                                             const float* __restrict__ trans,
                                             float* __restrict__ loss)
{
    __shared__ float Etr[LP * LP];
    __shared__ float ea_sm[LP];
    int lane = threadIdx.x;
    int b = blockIdx.x;
    int len = lens[b];

    for (int i = lane; i < LP * LP; i += 32) Etr[i] = expf(trans[i]);
    __syncwarp();

    const float* base = scores + (size_t)b * SEQ * LP;
    const int*   lab  = labels + b * SEQ;

    float g = 0.f;
    for (int t = lane; t < len; t += 32) {
        int c = lab[t];
        g += base[t * LP + c];
        if (t > 0) g += trans[c * LP + lab[t - 1]];
    }
    if (lane == 0) g += trans[lab[0] * LP + T] + trans[(LP - 1) * LP + lab[len - 1]];
#pragma unroll
    for (int o = 16; o; o >>= 1) g += __shfl_xor_sync(0xffffffffu, g, o);

    int r1 = (lane < 7) ? lane + 32 : 0;
    float al0 = -100.f;
    float al1 = (lane < 7) ? ((lane == 5) ? 0.f : -100.f) : -1e30f;

    float lg0 = base[lane];
    float lg1 = (lane < 7) ? base[32 + lane] : 0.f;
    for (int t = 0; t < SEQ; t++) {
        float nl0 = 0.f, nl1 = 0.f;
        if (t + 1 < SEQ) {
            nl0 = base[(t + 1) * LP + lane];
            nl1 = (lane < 7) ? base[(t + 1) * LP + 32 + lane] : 0.f;
        }
        float mx = fmaxf(al0, al1);
#pragma unroll
        for (int o = 16; o; o >>= 1) mx = fmaxf(mx, __shfl_xor_sync(0xffffffffu, mx, o));
        float e0 = expf(al0 - mx);
        float e1 = expf(al1 - mx);
        ea_sm[lane] = e0;
        if (lane < 7) ea_sm[32 + lane] = e1;
        __syncwarp();
        float s0 = 0.f, s0b = 0.f, s1 = 0.f, s1b = 0.f;
#pragma unroll
        for (int f = 0; f < 38; f += 2) {
            float eaf = ea_sm[f], eag = ea_sm[f + 1];
            s0  = fmaf(Etr[lane * LP + f],     eaf, s0);
            s0b = fmaf(Etr[lane * LP + f + 1], eag, s0b);
            s1  = fmaf(Etr[r1 * LP + f],       eaf, s1);
            s1b = fmaf(Etr[r1 * LP + f + 1],   eag, s1b);
        }
        s0 = fmaf(Etr[lane * LP + 38], ea_sm[38], s0) + s0b;
        s1 = fmaf(Etr[r1 * LP + 38],   ea_sm[38], s1) + s1b;
        if (t < len) {
            al0 = lg0 + mx + logf(s0);
            if (lane < 7) al1 = lg1 + mx + logf(s1);
        }
        __syncwarp();
        lg0 = nl0; lg1 = nl1;
    }

    al0 += trans[(LP - 1) * LP + lane];
    if (lane < 7) al1 += trans[(LP - 1) * LP + 32 + lane];
    float mx = fmaxf(al0, al1);
#pragma unroll
    for (int o = 16; o; o >>= 1) mx = fmaxf(mx, __shfl_xor_sync(0xffffffffu, mx, o));
    float e = expf(al0 - mx) + ((lane < 7) ? expf(al1 - mx) : 0.f);
#pragma unroll
    for (int o = 16; o; o >>= 1) e += __shfl_xor_sync(0xffffffffu, e, o);
    float norm = mx + logf(e);
    if (lane == 0) loss[b] = g - norm;
}

// =================================================================================
extern "C" void kernel_launch(void* const* d_in, const int* in_sizes, int n_in,
                              void* d_out, int out_size)
{
    const float* h      = (const float*)d_in[0];
    const int*   lens   = (const int*)d_in[2];
    const int*   labels = (const int*)d_in[3];
    const float* bio    = (const float*)d_in[4];
    const float* Wcat   = (const float*)d_in[5];
    const float* bcat   = (const float*)d_in[6];
    const float* Wcrf   = (const float*)d_in[7];
    const float* bcrf   = (const float*)d_in[8];
    const float* trans  = (const float*)d_in[9];

    float* out  = (float*)d_out;
    float* loss = out + ((size_t)out_size - NB);

    size_t smem1 = (size_t)T * H * sizeof(float);        // 151552
    size_t smem3 = (size_t)T * WPAD * sizeof(float);     // 152736
    cudaFuncSetAttribute(k1_attn,   cudaFuncAttributeMaxDynamicSharedMemorySize, (int)smem1);
    cudaFuncSetAttribute(k2_mma,    cudaFuncAttributeMaxDynamicSharedMemorySize, SM_TOT);
    cudaFuncSetAttribute(k3_logits, cudaFuncAttributeMaxDynamicSharedMemorySize, (int)smem3);

    kw_split <<<dim3(96, 32), dim3(32, 8)>>>(Wcat);
    k1_attn  <<<1024, 256, smem1>>>(h, bio);
    k2_mma   <<<dim3(4, 128), 256, SM_TOT>>>(bcat);
    k3_logits<<<128, 256, smem3>>>(Wcrf, bcrf, out);
    k4_crf   <<<NB, 32>>>(out, labels, lens, trans, loss);
}

// round 16
// speedup vs baseline: 1.1218x; 1.1218x over previous
#include <cuda_runtime.h>
#include <cuda_bf16.h>
#include <math.h>
#include <stdint.h>

#define ROWS 16384
#define H 1024
#define KTOT 3072
#define T 37
#define LP 39
#define SEQ 512
#define NB 32
#define WPAD 1032

// ---------------- scratch (static device memory; no allocations) ----------------
__device__ __align__(16) __nv_bfloat16 g_Ahi[(size_t)ROWS * KTOT];  // 96 MB
__device__ __align__(16) __nv_bfloat16 g_Alo[(size_t)ROWS * KTOT];  // 96 MB
__device__ __align__(16) __nv_bfloat16 g_Bhi[(size_t)H * KTOT];     // 6 MB  (W_cat^T hi)
__device__ __align__(16) __nv_bfloat16 g_Blo[(size_t)H * KTOT];     // 6 MB  (W_cat^T lo)
__device__ float g_y[(size_t)ROWS * H];                             // 64 MB

// ---------------- helpers ----------------
__device__ __forceinline__ uint32_t smem_u32(const void* p) {
    uint32_t a;
    asm("{ .reg .u64 t; cvta.to.shared.u64 t, %1; cvt.u32.u64 %0, t; }" : "=r"(a) : "l"(p));
    return a;
}
#define SMEM_SW(b) ((b) ^ (((b) >> 3) & 0x70))

__device__ __forceinline__ void cp16(uint32_t dst, const void* src) {
    asm volatile("cp.async.cg.shared.global [%0], [%1], 16;" :: "r"(dst), "l"(src) : "memory");
}

#define LDSM_X4(r0, r1, r2, r3, addr) \
    asm volatile("ldmatrix.sync.aligned.m8n8.x4.shared.b16 {%0,%1,%2,%3}, [%4];" \
        : "=r"(r0), "=r"(r1), "=r"(r2), "=r"(r3) : "r"(addr))

#define MMA16816(d, a, b) \
    asm volatile("mma.sync.aligned.m16n8k16.row.col.f32.bf16.bf16.f32 " \
        "{%0,%1,%2,%3}, {%4,%5,%6,%7}, {%8,%9}, {%0,%1,%2,%3};" \
        : "+f"(d[0]), "+f"(d[1]), "+f"(d[2]), "+f"(d[3]) \
        : "r"(a[0]), "r"(a[1]), "r"(a[2]), "r"(a[3]), "r"(b[0]), "r"(b[1]))

// split fp32x4 -> bf16 hi/lo packed
__device__ __forceinline__ void cvt_hilo(float4 v, uint2 &uhi, uint2 &ulo) {
    __nv_bfloat162 h01 = __floats2bfloat162_rn(v.x, v.y);
    __nv_bfloat162 h23 = __floats2bfloat162_rn(v.z, v.w);
    float2 f01 = __bfloat1622float2(h01), f23 = __bfloat1622float2(h23);
    __nv_bfloat162 l01 = __floats2bfloat162_rn(v.x - f01.x, v.y - f01.y);
    __nv_bfloat162 l23 = __floats2bfloat162_rn(v.z - f23.x, v.w - f23.y);
    uhi.x = *(uint32_t*)&h01; uhi.y = *(uint32_t*)&h23;
    ulo.x = *(uint32_t*)&l01; ulo.y = *(uint32_t*)&l23;
}

// =================================================================================
// KW: W_cat [3072,1024] fp32  ->  g_Bhi/g_Blo [1024,3072] bf16 (transposed split)
// =================================================================================
__global__ void kw_split(const float* __restrict__ W)
{
    __shared__ float tile[32][33];
    int k0 = blockIdx.x * 32, n0 = blockIdx.y * 32;
    int tx = threadIdx.x, ty = threadIdx.y;
    for (int r = ty; r < 32; r += 8) tile[r][tx] = W[(size_t)(k0 + r) * H + n0 + tx];
    __syncthreads();
    for (int r = ty; r < 32; r += 8) {
        float v = tile[tx][r];
        __nv_bfloat16 hi = __float2bfloat16(v);
        float lo = v - __bfloat162float(hi);
        size_t o = (size_t)(n0 + r) * KTOT + k0 + tx;
        g_Bhi[o] = hi;
        g_Blo[o] = __float2bfloat16(lo);
    }
}

// =================================================================================
// K1: attn over bio (37 classes); emits bf16 hi/lo of [h | aware | h*aware]
// =================================================================================
__global__ __launch_bounds__(256) void k1_attn(const float* __restrict__ h,
                                               const float* __restrict__ bio)
{
    extern __shared__ float bio_sm[];               // [37][1024]
    __shared__ float2 attn_sm[8][T];
    int tid = threadIdx.x;

    const float4* bio4 = (const float4*)bio;
    float4* bs4 = (float4*)bio_sm;
    for (int i = tid; i < T * H / 4; i += 256) bs4[i] = bio4[i];
    __syncthreads();

    int warp = tid >> 5, lane = tid & 31;
    int r0 = (blockIdx.x * 8 + warp) * 2;
    const float4* h0 = (const float4*)(h + (size_t)r0 * H);
    const float4* h1 = h0 + H / 4;
    float4 x0[8], x1[8];
#pragma unroll
    for (int i = 0; i < 8; i++) { x0[i] = h0[lane + 32*i]; x1[i] = h1[lane + 32*i]; }

    for (int t = 0; t < T; t++) {
        const float4* br = (const float4*)(bio_sm + t * H);
        float p0 = 0.f, p1 = 0.f;
#pragma unroll
        for (int i = 0; i < 8; i++) {
            float4 b = br[lane + 32*i];
            p0 += x0[i].x*b.x + x0[i].y*b.y + x0[i].z*b.z + x0[i].w*b.w;
            p1 += x1[i].x*b.x + x1[i].y*b.y + x1[i].z*b.z + x1[i].w*b.w;
        }
#pragma unroll
        for (int o = 16; o; o >>= 1) {
            p0 += __shfl_xor_sync(0xffffffffu, p0, o);
            p1 += __shfl_xor_sync(0xffffffffu, p1, o);
        }
        if (lane == 0) attn_sm[warp][t] = make_float2(p0 * 0.03125f, p1 * 0.03125f);
    }
    __syncwarp();

    float m0 = -1e30f, m1 = -1e30f;
    for (int t = 0; t < T; t++) { float2 v = attn_sm[warp][t]; m0 = fmaxf(m0, v.x); m1 = fmaxf(m1, v.y); }
    float sum0 = 0.f, sum1 = 0.f;
    for (int t = 0; t < T; t++) { float2 v = attn_sm[warp][t]; sum0 += expf(v.x - m0); sum1 += expf(v.y - m1); }
    float inv0 = 1.f / sum0, inv1 = 1.f / sum1;
    __syncwarp();
    for (int t = lane; t < T; t += 32) {
        float2 v = attn_sm[warp][t];
        attn_sm[warp][t] = make_float2(expf(v.x - m0) * inv0, expf(v.y - m1) * inv1);
    }
    __syncwarp();

    size_t ro0 = (size_t)r0 * KTOT, ro1 = (size_t)(r0 + 1) * KTOT;
#pragma unroll 2
    for (int i = 0; i < 8; i++) {
        float4 a0 = make_float4(0,0,0,0), a1 = make_float4(0,0,0,0);
        for (int t = 0; t < T; t++) {
            float2 at = attn_sm[warp][t];
            float4 b = ((const float4*)(bio_sm + t * H))[lane + 32*i];
            a0.x += at.x*b.x; a0.y += at.x*b.y; a0.z += at.x*b.z; a0.w += at.x*b.w;
            a1.x += at.y*b.x; a1.y += at.y*b.y; a1.z += at.y*b.z; a1.w += at.y*b.w;
        }
        float4 q0, q1;
        q0.x = x0[i].x*a0.x; q0.y = x0[i].y*a0.y; q0.z = x0[i].z*a0.z; q0.w = x0[i].w*a0.w;
        q1.x = x1[i].x*a1.x; q1.y = x1[i].y*a1.y; q1.z = x1[i].z*a1.z; q1.w = x1[i].w*a1.w;

        int col = (lane + 32*i) * 4;
        uint2 uh, ul;
        cvt_hilo(x0[i], uh, ul);
        *(uint2*)(g_Ahi + ro0 + col) = uh; *(uint2*)(g_Alo + ro0 + col) = ul;
        cvt_hilo(x1[i], uh, ul);
        *(uint2*)(g_Ahi + ro1 + col) = uh; *(uint2*)(g_Alo + ro1 + col) = ul;
        cvt_hilo(a0, uh, ul);
        *(uint2*)(g_Ahi + ro0 + 1024 + col) = uh; *(uint2*)(g_Alo + ro0 + 1024 + col) = ul;
        cvt_hilo(a1, uh, ul);
        *(uint2*)(g_Ahi + ro1 + 1024 + col) = uh; *(uint2*)(g_Alo + ro1 + 1024 + col) = ul;
        cvt_hilo(q0, uh, ul);
        *(uint2*)(g_Ahi + ro0 + 2048 + col) = uh; *(uint2*)(g_Alo + ro0 + 2048 + col) = ul;
        cvt_hilo(q1, uh, ul);
        *(uint2*)(g_Ahi + ro1 + 2048 + col) = uh; *(uint2*)(g_Alo + ro1 + 2048 + col) = ul;
    }
}

// =================================================================================
// K2: y = gelu( x @ W_cat + b ), fused split-3: per k-tile load Ahi/Alo/Bhi/Blo
// ONCE and accumulate Ahi*Bhi + Ahi*Blo + Alo*Bhi. BM=BN=128, BK=64, NS=2.
// Traffic: 3.2 GB total (vs 4.8 GB in the 3-segment K-loop).
// =================================================================================
#define BM 128
#define BN 128
#define BK 64
#define NS 2
#define KTILES 48          /* 3072 / 64 */
#define OFF_AHI 0
#define OFF_ALO 16384
#define OFF_BHI 32768
#define OFF_BLO 49152
#define SM_STG  65536
#define SM_TOT  (NS * SM_STG)                 /* 131072 */

__device__ __forceinline__ void load_tile(uint32_t sb, int slot, int kt,
                                          int m0, int n0, int tid)
{
    int kk = kt * 64;
    uint32_t base = sb + slot * SM_STG;
#pragma unroll
    for (int j = 0; j < 4; j++) {
        int idx = tid + j * 256;
        int row = idx >> 3, ch = idx & 7;
        uint32_t off = SMEM_SW((uint32_t)(row * 128 + ch * 16));
        size_t aoff = (size_t)(m0 + row) * KTOT + kk + ch * 8;
        size_t boff = (size_t)(n0 + row) * KTOT + kk + ch * 8;
        cp16(base + OFF_AHI + off, g_Ahi + aoff);
        cp16(base + OFF_ALO + off, g_Alo + aoff);
        cp16(base + OFF_BHI + off, g_Bhi + boff);
        cp16(base + OFF_BLO + off, g_Blo + boff);
    }
}

__global__ __launch_bounds__(256, 1) void k2_mma(const float* __restrict__ bias)
{
    extern __shared__ char smem[];
    uint32_t sb = smem_u32(smem);
    int tid = threadIdx.x, warp = tid >> 5, lane = tid & 31;
    int m0 = blockIdx.y * BM, n0 = blockIdx.x * BN;
    int wm = warp & 3, wn = warp >> 2;        // warp tile (wm*32, wn*64)

    float acc[2][8][4];
#pragma unroll
    for (int mi = 0; mi < 2; mi++)
#pragma unroll
        for (int ni = 0; ni < 8; ni++)
#pragma unroll
            for (int j = 0; j < 4; j++) acc[mi][ni][j] = 0.f;

    int a_row = (lane & 7) + ((lane >> 3) & 1) * 8;   // 0..15
    int a_kch = lane >> 4;                            // 0..1
    int b_row = (lane & 7) + (lane >> 4) * 8;         // n 0..15
    int b_kch = (lane >> 3) & 1;                      // 0..1

    // prologue: tiles 0,1
#pragma unroll
    for (int p = 0; p < NS; p++) {
        load_tile(sb, p, p, m0, n0, tid);
        asm volatile("cp.async.commit_group;" ::: "memory");
    }

    for (int kt = 0; kt < KTILES; kt++) {
        int slot = kt & 1;
        if (kt < KTILES - 1) asm volatile("cp.async.wait_group 1;" ::: "memory");
        else                 asm volatile("cp.async.wait_group 0;" ::: "memory");
        __syncthreads();

        uint32_t base = sb + slot * SM_STG;
#pragma unroll
        for (int ks = 0; ks < 4; ks++) {
            uint32_t Ahi[2][4], Alo[2][4];
#pragma unroll
            for (int mi = 0; mi < 2; mi++) {
                int row = wm * 32 + mi * 16 + a_row;
                uint32_t off = SMEM_SW((uint32_t)(row * 128 + ks * 32 + a_kch * 16));
                LDSM_X4(Ahi[mi][0], Ahi[mi][1], Ahi[mi][2], Ahi[mi][3], base + OFF_AHI + off);
                LDSM_X4(Alo[mi][0], Alo[mi][1], Alo[mi][2], Alo[mi][3], base + OFF_ALO + off);
            }
            uint32_t Bhi[8][2], Blo[8][2];
#pragma unroll
            for (int np = 0; np < 4; np++) {
                int row = wn * 64 + np * 16 + b_row;
                uint32_t off = SMEM_SW((uint32_t)(row * 128 + ks * 32 + b_kch * 16));
                uint32_t r0, r1, r2, r3;
                LDSM_X4(r0, r1, r2, r3, base + OFF_BHI + off);
                Bhi[np*2][0] = r0;   Bhi[np*2][1] = r1;
                Bhi[np*2+1][0] = r2; Bhi[np*2+1][1] = r3;
                LDSM_X4(r0, r1, r2, r3, base + OFF_BLO + off);
                Blo[np*2][0] = r0;   Blo[np*2][1] = r1;
                Blo[np*2+1][0] = r2; Blo[np*2+1][1] = r3;
            }
#pragma unroll
            for (int mi = 0; mi < 2; mi++)
#pragma unroll
                for (int ni = 0; ni < 8; ni++) {
                    MMA16816(acc[mi][ni], Ahi[mi], Bhi[ni]);
                    MMA16816(acc[mi][ni], Ahi[mi], Blo[ni]);
                    MMA16816(acc[mi][ni], Alo[mi], Bhi[ni]);
                }
        }
        __syncthreads();   // all warps done with slot before refill

        if (kt + NS < KTILES) {
            load_tile(sb, slot, kt + NS, m0, n0, tid);
            asm volatile("cp.async.commit_group;" ::: "memory");
        }
    }

    // epilogue: + bias, exact gelu, store
    int g = lane >> 2, tig = lane & 3;
#pragma unroll
    for (int mi = 0; mi < 2; mi++) {
        int row0 = m0 + wm * 32 + mi * 16 + g;
#pragma unroll
        for (int ni = 0; ni < 8; ni++) {
            int col = n0 + wn * 64 + ni * 8 + tig * 2;
            float2 bv = *(const float2*)&bias[col];
            float x, y0v, y1v;
            x = acc[mi][ni][0] + bv.x; y0v = 0.5f * x * (1.f + erff(x * 0.70710678118654752440f));
            x = acc[mi][ni][1] + bv.y; y1v = 0.5f * x * (1.f + erff(x * 0.70710678118654752440f));
            *(float2*)(g_y + (size_t)row0 * H + col) = make_float2(y0v, y1v);
            x = acc[mi][ni][2] + bv.x; y0v = 0.5f * x * (1.f + erff(x * 0.70710678118654752440f));
            x = acc[mi][ni][3] + bv.y; y1v = 0.5f * x * (1.f + erff(x * 0.70710678118654752440f));
            *(float2*)(g_y + (size_t)(row0 + 8) * H + col) = make_float2(y0v, y1v);
        }
    }
}

// =================================================================================
// K3: logits = y @ W_crf + b_crf ; ner_scores = [logits | -1e4 pads] (B*S x 39)
// =================================================================================
__global__ __launch_bounds__(256) void k3_logits(const float* __restrict__ Wc,
                                                 const float* __restrict__ bc,
                                                 float* __restrict__ out)
{
    extern __shared__ float wsm[];   // [37][WPAD]
    int tid = threadIdx.x;
    for (int i = tid; i < H * T; i += 256) {
        int k = i / T, t = i - k * T;
        wsm[t * WPAD + k] = Wc[i];
    }
    __syncthreads();

    int warp = tid >> 5, lane = tid & 31;
    int slot = blockIdx.x * 8 + warp;
    for (int rep = 0; rep < 8; rep++) {
        int r0 = slot * 16 + rep * 2;
        const float4* y0 = (const float4*)(g_y + (size_t)r0 * H);
        const float4* y1 = y0 + H / 4;
        float4 x0[8], x1[8];
#pragma unroll
        for (int i = 0; i < 8; i++) { x0[i] = y0[lane + 32*i]; x1[i] = y1[lane + 32*i]; }
        for (int t = 0; t < T; t++) {
            const float4* wr = (const float4*)(wsm + t * WPAD);
            float p0 = 0.f, p1 = 0.f;
#pragma unroll
            for (int i = 0; i < 8; i++) {
                float4 w = wr[lane + 32*i];
                p0 += x0[i].x*w.x + x0[i].y*w.y + x0[i].z*w.z + x0[i].w*w.w;
                p1 += x1[i].x*w.x + x1[i].y*w.y + x1[i].z*w.z + x1[i].w*w.w;
            }
#pragma unroll
            for (int o = 16; o; o >>= 1) {
                p0 += __shfl_xor_sync(0xffffffffu, p0, o);
                p1 += __shfl_xor_sync(0xffffffffu, p1, o);
            }
            if (lane == 0) {
                float bt = __ldg(&bc[t]);
                out[(size_t)r0 * LP + t]       = p0 + bt;
                out[(size_t)(r0 + 1) * LP + t] = p1 + bt;
            }
        }
        if (lane < 2) {
            out[(size_t)r0 * LP + T + lane]       = -10000.f;
            out[(size_t)(r0 + 1) * LP + T + lane] = -10000.f;
        }
    }
}

// =================================================================================
// K4: CRF log-likelihood; one warp per batch (R11 version)
// =================================================================================
__global__ __launch_bounds__(32) void k4_crf(const float* __restrict__ scores,
                                             const int* __restrict__ labels,
                                             const int* __restrict__ lens,
                                             const float* __restrict__ trans,
                                             float* __restrict__ loss)
{
    __shared__ float Etr[LP * LP];
    __shared__ float ea_sm[LP];
    int lane = threadIdx.x;
    int b = blockIdx.x;
    int len = lens[b];

    for (int i = lane; i < LP * LP; i += 32) Etr[i] = expf(trans[i]);
    __syncwarp();

    const float* base = scores + (size_t)b * SEQ * LP;
    const int*   lab  = labels + b * SEQ;

    float g = 0.f;
    for (int t = lane; t < len; t += 32) {
        int c = lab[t];
        g += base[t * LP + c];
        if (t > 0) g += trans[c * LP + lab[t - 1]];
    }
    if (lane == 0) g += trans[lab[0] * LP + T] + trans[(LP - 1) * LP + lab[len - 1]];
#pragma unroll
    for (int o = 16; o; o >>= 1) g += __shfl_xor_sync(0xffffffffu, g, o);

    int r1 = (lane < 7) ? lane + 32 : 0;
    float al0 = -100.f;
    float al1 = (lane < 7) ? ((lane == 5) ? 0.f : -100.f) : -1e30f;

    float lg0 = base[lane];
    float lg1 = (lane < 7) ? base[32 + lane] : 0.f;
    for (int t = 0; t < SEQ; t++) {
        float nl0 = 0.f, nl1 = 0.f;
        if (t + 1 < SEQ) {
            nl0 = base[(t + 1) * LP + lane];
            nl1 = (lane < 7) ? base[(t + 1) * LP + 32 + lane] : 0.f;
        }
        float mx = fmaxf(al0, al1);
#pragma unroll
        for (int o = 16; o; o >>= 1) mx = fmaxf(mx, __shfl_xor_sync(0xffffffffu, mx, o));
        float e0 = expf(al0 - mx);
        float e1 = expf(al1 - mx);
        ea_sm[lane] = e0;
        if (lane < 7) ea_sm[32 + lane] = e1;
        __syncwarp();
        float s0 = 0.f, s0b = 0.f, s1 = 0.f, s1b = 0.f;
#pragma unroll
        for (int f = 0; f < 38; f += 2) {
            float eaf = ea_sm[f], eag = ea_sm[f + 1];
            s0  = fmaf(Etr[lane * LP + f],     eaf, s0);
            s0b = fmaf(Etr[lane * LP + f + 1], eag, s0b);
            s1  = fmaf(Etr[r1 * LP + f],       eaf, s1);
            s1b = fmaf(Etr[r1 * LP + f + 1],   eag, s1b);
        }
        s0 = fmaf(Etr[lane * LP + 38], ea_sm[38], s0) + s0b;
        s1 = fmaf(Etr[r1 * LP + 38],   ea_sm[38], s1) + s1b;
        if (t < len) {
            al0 = lg0 + mx + logf(s0);
            if (lane < 7) al1 = lg1 + mx + logf(s1);
        }
        __syncwarp();
        lg0 = nl0; lg1 = nl1;
    }

    al0 += trans[(LP - 1) * LP + lane];
    if (lane < 7) al1 += trans[(LP - 1) * LP + 32 + lane];
    float mx = fmaxf(al0, al1);
#pragma unroll
    for (int o = 16; o; o >>= 1) mx = fmaxf(mx, __shfl_xor_sync(0xffffffffu, mx, o));
    float e = expf(al0 - mx) + ((lane < 7) ? expf(al1 - mx) : 0.f);
#pragma unroll
    for (int o = 16; o; o >>= 1) e += __shfl_xor_sync(0xffffffffu, e, o);
    float norm = mx + logf(e);
    if (lane == 0) loss[b] = g - norm;
}

// =================================================================================
extern "C" void kernel_launch(void* const* d_in, const int* in_sizes, int n_in,
                              void* d_out, int out_size)
{
    const float* h      = (const float*)d_in[0];
    const int*   lens   = (const int*)d_in[2];
    const int*   labels = (const int*)d_in[3];
    const float* bio    = (const float*)d_in[4];
    const float* Wcat   = (const float*)d_in[5];
    const float* bcat   = (const float*)d_in[6];
    const float* Wcrf   = (const float*)d_in[7];
    const float* bcrf   = (const float*)d_in[8];
    const float* trans  = (const float*)d_in[9];

    float* out  = (float*)d_out;
    float* loss = out + ((size_t)out_size - NB);

    size_t smem1 = (size_t)T * H * sizeof(float);        // 151552
    size_t smem3 = (size_t)T * WPAD * sizeof(float);     // 152736
    cudaFuncSetAttribute(k1_attn,   cudaFuncAttributeMaxDynamicSharedMemorySize, (int)smem1);
    cudaFuncSetAttribute(k2_mma,    cudaFuncAttributeMaxDynamicSharedMemorySize, SM_TOT);
    cudaFuncSetAttribute(k3_logits, cudaFuncAttributeMaxDynamicSharedMemorySize, (int)smem3);

    kw_split <<<dim3(96, 32), dim3(32, 8)>>>(Wcat);
    k1_attn  <<<1024, 256, smem1>>>(h, bio);
    k2_mma   <<<dim3(8, 128), 256, SM_TOT>>>(bcat);
    k3_logits<<<128, 256, smem3>>>(Wcrf, bcrf, out);
    k4_crf   <<<NB, 32>>>(out, labels, lens, trans, loss);
}